// round 16
// baseline (speedup 1.0000x reference)
#include <cuda_runtime.h>
#include <cuda_bf16.h>
#include <cstdint>

// Problem constants
#define BB    2
#define TT    2048
#define DD    1024
#define HH    16
#define DH    64
#define BT    (BB*TT)          // 4096
#define KBIG  3072             // 3 * DD (split-in-K bf16 GEMM)
#define NELE  ((size_t)BT*DD)  // 4,194,304

// ---------------------------------------------------------------------------
// Scratch (no cudaMalloc allowed -> __device__ globals)
// ---------------------------------------------------------------------------
__device__ float g_qpre[NELE];
__device__ float g_kpre[NELE];
__device__ float g_vpre[NELE];
__device__ float g_gpre[NELE];
__device__ float g_qn[NELE];
__device__ float g_kn[NELE];
__device__ float g_vn[NELE];
__device__ float g_o[NELE];
__device__ float g_beta[BT*HH];
__device__ float g_bpre[(size_t)BT*128];   // beta pre-activation (cols 0..15 used)

// bf16 split operands for tensor-core GEMMs
__device__ __align__(16) __nv_bfloat16 g_Ax[(size_t)BT*KBIG];      // [Ah|Al|Ah] of x
__device__ __align__(16) __nv_bfloat16 g_Ao[(size_t)BT*KBIG];      // [Ah|Al|Ah] of o*gate
__device__ __align__(16) __nv_bfloat16 g_Bw[5][(size_t)DD*KBIG];   // W^T splits: [Bh|Bh|Bl]
__device__ __align__(16) __nv_bfloat16 g_Bwb[(size_t)128*KBIG];    // Wb^T split (16 rows + zeros)

// ---------------------------------------------------------------------------
// Small helpers
// ---------------------------------------------------------------------------
__device__ __forceinline__ uint32_t smem_u32(const void* p) {
    uint32_t a;
    asm("{ .reg .u64 t; cvta.to.shared.u64 t, %1; cvt.u32.u64 %0, t; }"
        : "=r"(a) : "l"(p));
    return a;
}
__device__ __forceinline__ unsigned sw128(unsigned o) { return o ^ ((o >> 3) & 0x70); }
__device__ __forceinline__ void cpa16(unsigned dst, const void* src) {
    asm volatile("cp.async.cg.shared.global [%0], [%1], 16;\n" ::"r"(dst), "l"(src));
}
__device__ __forceinline__ void ldsm4(uint32_t* r, uint32_t addr) {
    asm volatile("ldmatrix.sync.aligned.m8n8.x4.shared.b16 {%0,%1,%2,%3}, [%4];"
                 : "=r"(r[0]), "=r"(r[1]), "=r"(r[2]), "=r"(r[3]) : "r"(addr));
}
__device__ __forceinline__ void mma_bf16(float* d, const uint32_t* a, const uint32_t* b) {
    asm volatile(
        "mma.sync.aligned.m16n8k16.row.col.f32.bf16.bf16.f32 "
        "{%0,%1,%2,%3}, {%4,%5,%6,%7}, {%8,%9}, {%0,%1,%2,%3};"
        : "+f"(d[0]), "+f"(d[1]), "+f"(d[2]), "+f"(d[3])
        : "r"(a[0]), "r"(a[1]), "r"(a[2]), "r"(a[3]), "r"(b[0]), "r"(b[1]));
}

// ---------------------------------------------------------------------------
// Split kernels: x -> g_Ax ([hi|lo|hi]),  W -> W^T splits ([hi|hi|lo])
// ---------------------------------------------------------------------------
__global__ __launch_bounds__(256) void split_x(const float* __restrict__ x) {
    int row = blockIdx.x;
    int c0  = threadIdx.x * 4;
    float4 v = *(const float4*)(x + (size_t)row * DD + c0);
    float vv[4] = {v.x, v.y, v.z, v.w};
    size_t b = (size_t)row * KBIG + c0;
#pragma unroll
    for (int j = 0; j < 4; j++) {
        __nv_bfloat16 hi = __float2bfloat16(vv[j]);
        __nv_bfloat16 lo = __float2bfloat16(vv[j] - __bfloat162float(hi));
        g_Ax[b + j]          = hi;
        g_Ax[b + DD + j]     = lo;
        g_Ax[b + 2 * DD + j] = hi;
    }
}

__global__ __launch_bounds__(1024) void split_w(const float* __restrict__ Wq,
                                                const float* __restrict__ Wk,
                                                const float* __restrict__ Wv,
                                                const float* __restrict__ Wg,
                                                const float* __restrict__ Wo) {
    const float* W;
    switch (blockIdx.z) {
        case 0: W = Wq; break;
        case 1: W = Wk; break;
        case 2: W = Wv; break;
        case 3: W = Wg; break;
        default: W = Wo; break;
    }
    __nv_bfloat16* Bt = g_Bw[blockIdx.z];
    __shared__ float tile[32][33];
    int tx = threadIdx.x, ty = threadIdx.y;
    int k = blockIdx.y * 32 + ty, n = blockIdx.x * 32 + tx;
    tile[ty][tx] = W[(size_t)k * DD + n];
    __syncthreads();
    int nn = blockIdx.x * 32 + ty, kk = blockIdx.y * 32 + tx;
    float v = tile[tx][ty];  // = W[kk][nn]
    __nv_bfloat16 hi = __float2bfloat16(v);
    __nv_bfloat16 lo = __float2bfloat16(v - __bfloat162float(hi));
    size_t b = (size_t)nn * KBIG + kk;
    Bt[b]          = hi;
    Bt[b + DD]     = hi;
    Bt[b + 2 * DD] = lo;
}

// Wb (1024,16) -> g_Bwb rows 0..15 = [hi|hi|lo] of Wb columns; rows 16..127 zero.
__global__ __launch_bounds__(256) void split_wb(const float* __restrict__ Wb) {
    int n = blockIdx.x;  // 0..127
    __nv_bfloat16* row = g_Bwb + (size_t)n * KBIG;
    if (n < 16) {
        for (int k = threadIdx.x; k < DD; k += 256) {
            float v = Wb[(size_t)k * HH + n];
            __nv_bfloat16 hi = __float2bfloat16(v);
            __nv_bfloat16 lo = __float2bfloat16(v - __bfloat162float(hi));
            row[k]          = hi;
            row[k + DD]     = hi;
            row[k + 2 * DD] = lo;
        }
    } else {
        for (int k = threadIdx.x; k < KBIG; k += 256)
            row[k] = __float2bfloat16(0.f);
    }
}

// sigmoid on the 16 real beta columns
__global__ __launch_bounds__(256) void beta_sig() {
    int idx = blockIdx.x * 256 + threadIdx.x;   // 0..65535
    int bt = idx >> 4, h = idx & 15;
    float v = g_bpre[(size_t)bt * 128 + h];
    g_beta[(size_t)bt * HH + h] = 1.f / (1.f + expf(-v));
}

// ---------------------------------------------------------------------------
// bf16 tensor-core GEMM via mma.sync (portable HMMA; tcgen05 PTX rejected by
// this harness's .target sm_103).
// C[M,N] = A[M,KBIG] * Bt[N,KBIG]^T, fp32 out, row stride ldc.
// CTA tile 128x128, BK=64, SW128 smem, 3-stage cp.async ring, one bar/stage.
// __launch_bounds__(256,2): 2 CTAs/SM.
// ---------------------------------------------------------------------------
#define GBM   128
#define GBN   128
#define GBK   64
#define NSTG  3
#define NS    (KBIG/GBK)            // 48
#define STG_A (GBM*128)             // 16384 B
#define STG_B (GBN*128)             // 16384 B
#define STG_BYTES (STG_A + STG_B)   // 32768 B
#define DSM_BYTES (NSTG*STG_BYTES + 1024)

__device__ __forceinline__ void gemm_mma_body(const __nv_bfloat16* __restrict__ A,
                                              const __nv_bfloat16* __restrict__ Bt,
                                              float* __restrict__ C, int ldc) {
    extern __shared__ char dynsm[];
    const uint32_t smb = (smem_u32(dynsm) + 1023u) & ~1023u;
    const int tid = threadIdx.x;
    const int wid = tid >> 5, lid = tid & 31;
    const int bm = blockIdx.y * GBM;
    const int bn = blockIdx.x * GBN;
    const int wm = (wid & 3) * 32;
    const int wn = (wid >> 2) * 64;

    float acc[2][8][4];
#pragma unroll
    for (int i = 0; i < 2; i++)
#pragma unroll
        for (int j = 0; j < 8; j++)
#pragma unroll
            for (int q = 0; q < 4; q++) acc[i][j][q] = 0.f;

    auto load_stage = [&](int st, int slot) {
        unsigned baseA = smb + slot * STG_BYTES;
        unsigned baseB = baseA + STG_A;
        const __nv_bfloat16* Ab = A + (size_t)bm * KBIG + st * GBK;
        const __nv_bfloat16* Bb = Bt + (size_t)bn * KBIG + st * GBK;
#pragma unroll
        for (int c = tid; c < 1024; c += 256) {
            int r = c >> 3, ci = c & 7;
            cpa16(baseA + sw128(r * 128 + ci * 16), Ab + (size_t)r * KBIG + ci * 8);
        }
#pragma unroll
        for (int c = tid; c < 1024; c += 256) {
            int r = c >> 3, ci = c & 7;
            cpa16(baseB + sw128(r * 128 + ci * 16), Bb + (size_t)r * KBIG + ci * 8);
        }
    };

    const int a_row = (lid & 15);
    const int a_kb  = (lid >> 4) * 16;
    const int b_row = (lid & 7) + (lid >> 4) * 8;
    const int b_kb  = ((lid >> 3) & 1) * 16;

    load_stage(0, 0);
    asm volatile("cp.async.commit_group;\n" ::: "memory");
    load_stage(1, 1);
    asm volatile("cp.async.commit_group;\n" ::: "memory");

    for (int i = 0; i < NS; i++) {
        const int slot = i % NSTG;
        asm volatile("cp.async.wait_group 1;\n" ::: "memory");
        __syncthreads();

        if (i + 2 < NS) load_stage(i + 2, (i + 2) % NSTG);
        asm volatile("cp.async.commit_group;\n" ::: "memory");

        const unsigned baseA = smb + slot * STG_BYTES;
        const unsigned baseB = baseA + STG_A;

#pragma unroll
        for (int ks = 0; ks < 4; ks++) {
            uint32_t af[2][4];
#pragma unroll
            for (int mt = 0; mt < 2; mt++)
                ldsm4(af[mt],
                      baseA + sw128((wm + mt * 16 + a_row) * 128 + ks * 32 + a_kb));
            uint32_t bfr[4][4];
#pragma unroll
            for (int nt = 0; nt < 4; nt++)
                ldsm4(bfr[nt],
                      baseB + sw128((wn + nt * 16 + b_row) * 128 + ks * 32 + b_kb));
#pragma unroll
            for (int mt = 0; mt < 2; mt++)
#pragma unroll
                for (int n8 = 0; n8 < 8; n8++)
                    mma_bf16(acc[mt][n8], af[mt], &bfr[n8 >> 1][(n8 & 1) * 2]);
        }
    }

    const int g   = lid >> 2;
    const int tig = lid & 3;
#pragma unroll
    for (int mt = 0; mt < 2; mt++) {
#pragma unroll
        for (int n8 = 0; n8 < 8; n8++) {
            int row = bm + wm + mt * 16 + g;
            int col = bn + wn + n8 * 8 + tig * 2;
            float2 lo = make_float2(acc[mt][n8][0], acc[mt][n8][1]);
            float2 hi = make_float2(acc[mt][n8][2], acc[mt][n8][3]);
            *(float2*)(C + (size_t)row * ldc + col)       = lo;
            *(float2*)(C + (size_t)(row + 8) * ldc + col) = hi;
        }
    }
}

// z = 0..3: q/k/v/g projections (N=1024). z = 4: beta slice (N=128, x-tile 0 only).
__global__ __launch_bounds__(256, 2) void proj_mma() {
    if (blockIdx.z == 4) {
        if (blockIdx.x != 0) return;
        gemm_mma_body(g_Ax, g_Bwb, g_bpre, 128);
        return;
    }
    float* C;
    switch (blockIdx.z) {
        case 0:  C = g_qpre; break;
        case 1:  C = g_kpre; break;
        case 2:  C = g_vpre; break;
        default: C = g_gpre; break;
    }
    gemm_mma_body(g_Ax, g_Bw[blockIdx.z], C, DD);
}

__global__ __launch_bounds__(256, 2) void out_mma(float* __restrict__ out) {
    gemm_mma_body(g_Ao, g_Bw[4], out, DD);
}

// ---------------------------------------------------------------------------
// Depthwise causal conv(k=4) + bias + silu, then (for q,k) per-head l2norm.
// Fused: blockIdx.z = mode (0=q, 1=k, 2=v).
// ---------------------------------------------------------------------------
__global__ __launch_bounds__(256) void conv_norm(const float* __restrict__ cq_w,
                                                 const float* __restrict__ cq_b,
                                                 const float* __restrict__ ck_w,
                                                 const float* __restrict__ ck_b,
                                                 const float* __restrict__ cv_w,
                                                 const float* __restrict__ cv_b) {
    int mode = blockIdx.z;
    const float* pre = (mode == 0) ? g_qpre : (mode == 1) ? g_kpre : g_vpre;
    float* out       = (mode == 0) ? g_qn   : (mode == 1) ? g_kn   : g_vn;
    const float* cw  = (mode == 0) ? cq_w   : (mode == 1) ? ck_w   : cv_w;
    const float* cb  = (mode == 0) ? cq_b   : (mode == 1) ? ck_b   : cv_b;

    int blk = blockIdx.x;
    int hq  = blk & 3;
    int bt  = blk >> 2;
    int t   = bt & (TT - 1);
    int b   = bt >> 11;
    int tid = threadIdx.x;
    int hh  = tid >> 6;
    int ch  = hq * 256 + tid;

    float acc = cb[ch];
#pragma unroll
    for (int j = 0; j < 4; j++) {
        int tt = t - 3 + j;
        if (tt >= 0)
            acc = fmaf(pre[(size_t)(b * TT + tt) * DD + ch], cw[ch * 4 + j], acc);
    }
    float y = acc / (1.f + expf(-acc));  // silu

    if (mode < 2) {
        float ss = y * y;
#pragma unroll
        for (int m = 16; m; m >>= 1) ss += __shfl_xor_sync(0xffffffffu, ss, m);
        __shared__ float red[8];
        if ((tid & 31) == 0) red[tid >> 5] = ss;
        __syncthreads();
        float tot = red[hh * 2] + red[hh * 2 + 1];
        float inv = rsqrtf(tot + 1e-6f);
        if (mode == 0) inv *= 0.125f;
        y *= inv;
    }
    out[(size_t)bt * DD + ch] = y;
}

// ---------------------------------------------------------------------------
// Sequential delta-rule scan — WARP-AUTONOMOUS, no smem, no barriers.
// Warp = one (b, h, 4-column v-slice). lane = grp*4 + col: grp=0..7 owns rows
// grp*8..grp*8+7 (8 state floats), col=0..3 selects the v-column.
// Reductions over the 8 grps = butterfly xor {4, 8, 16} (col-preserving).
// Inputs prefetched into registers with distance 2 (rotating 3-buffer,
// manually 3-way unrolled so all buffer indices are compile-time constants).
// ---------------------------------------------------------------------------
#define SCAN_STEP(t, CUR, NXT) do {                                              \
    float4 k0 = kb0[CUR], k1 = kb1[CUR];                                         \
    float4 q0 = qb0[CUR], q1 = qb1[CUR];                                         \
    float vt = vb[CUR], btv = bbf[CUR];                                          \
    int tn = (t) + 2;                                                            \
    if (tn < TT) {                                                               \
        const float4* kr = (const float4*)(Kp + (size_t)tn * DD);                \
        kb0[NXT] = kr[0]; kb1[NXT] = kr[1];                                      \
        const float4* qr = (const float4*)(Qp + (size_t)tn * DD);                \
        qb0[NXT] = qr[0]; qb1[NXT] = qr[1];                                      \
        vb[NXT]  = Vp[(size_t)tn * DD];                                          \
        bbf[NXT] = Bp[(size_t)tn * HH];                                          \
    }                                                                            \
    float p  = fmaf(k0.x, s0, fmaf(k0.y, s1, fmaf(k0.z, s2, fmaf(k0.w, s3,      \
               fmaf(k1.x, s4, fmaf(k1.y, s5, fmaf(k1.z, s6, k1.w * s7)))))));   \
    float po = fmaf(q0.x, s0, fmaf(q0.y, s1, fmaf(q0.z, s2, fmaf(q0.w, s3,      \
               fmaf(q1.x, s4, fmaf(q1.y, s5, fmaf(q1.z, s6, q1.w * s7)))))));   \
    float qk = fmaf(q0.x, k0.x, fmaf(q0.y, k0.y, fmaf(q0.z, k0.z,               \
               fmaf(q0.w, k0.w, fmaf(q1.x, k1.x, fmaf(q1.y, k1.y,               \
               fmaf(q1.z, k1.z, q1.w * k1.w)))))));                             \
    p  += __shfl_xor_sync(0xffffffffu, p, 4);                                    \
    po += __shfl_xor_sync(0xffffffffu, po, 4);                                   \
    qk += __shfl_xor_sync(0xffffffffu, qk, 4);                                   \
    p  += __shfl_xor_sync(0xffffffffu, p, 8);                                    \
    po += __shfl_xor_sync(0xffffffffu, po, 8);                                   \
    qk += __shfl_xor_sync(0xffffffffu, qk, 8);                                   \
    p  += __shfl_xor_sync(0xffffffffu, p, 16);                                   \
    po += __shfl_xor_sync(0xffffffffu, po, 16);                                  \
    qk += __shfl_xor_sync(0xffffffffu, qk, 16);                                  \
    float err = (vt - p) * btv;                                                  \
    if (grp == 0) Op[(size_t)(t) * DD] = fmaf(qk, err, po);                      \
    s0 = fmaf(k0.x, err, s0); s1 = fmaf(k0.y, err, s1);                          \
    s2 = fmaf(k0.z, err, s2); s3 = fmaf(k0.w, err, s3);                          \
    s4 = fmaf(k1.x, err, s4); s5 = fmaf(k1.y, err, s5);                          \
    s6 = fmaf(k1.z, err, s6); s7 = fmaf(k1.w, err, s7);                          \
} while (0)

__global__ __launch_bounds__(32) void scan_kernel() {
    int w   = blockIdx.x;        // 0..511
    int sv  = w & 15;            // 4-column v-slice
    int bh  = w >> 4;
    int b   = bh >> 4, h = bh & 15;
    int lane = threadIdx.x;
    int grp = lane >> 2;         // 0..7 -> rows grp*8..grp*8+7
    int col = lane & 3;          // 0..3
    int v0  = sv * 4;

    const size_t base = (size_t)b * TT * DD + h * DH;
    const float* Kp = g_kn + base + grp * 8;
    const float* Qp = g_qn + base + grp * 8;
    const float* Vp = g_vn + base + v0 + col;
    const float* Bp = g_beta + (size_t)b * TT * HH + h;
    float* Op = g_o + base + v0 + col;

    float s0 = 0.f, s1 = 0.f, s2 = 0.f, s3 = 0.f;
    float s4 = 0.f, s5 = 0.f, s6 = 0.f, s7 = 0.f;

    float4 kb0[3], kb1[3], qb0[3], qb1[3];
    float  vb[3], bbf[3];

    // prologue: fill buffers 0 and 1 (t = 0, 1)
    {
        const float4* kr = (const float4*)(Kp);
        kb0[0] = kr[0]; kb1[0] = kr[1];
        const float4* qr = (const float4*)(Qp);
        qb0[0] = qr[0]; qb1[0] = qr[1];
        vb[0]  = Vp[0];
        bbf[0] = Bp[0];
        const float4* kr1 = (const float4*)(Kp + DD);
        kb0[1] = kr1[0]; kb1[1] = kr1[1];
        const float4* qr1 = (const float4*)(Qp + DD);
        qb0[1] = qr1[0]; qb1[1] = qr1[1];
        vb[1]  = Vp[DD];
        bbf[1] = Bp[HH];
    }

    for (int tt = 0; tt < TT - 2; tt += 3) {
        SCAN_STEP(tt,     0, 2);
        SCAN_STEP(tt + 1, 1, 0);
        SCAN_STEP(tt + 2, 2, 1);
    }
    // TT = 2048 = 3*682 + 2 -> tail t = 2046 (%3==0), 2047 (%3==1)
    SCAN_STEP(TT - 2, 0, 2);
    SCAN_STEP(TT - 1, 1, 0);
}

// ---------------------------------------------------------------------------
// RMSNorm over head_dim + silu gate -> bf16 split rows of g_Ao
// ---------------------------------------------------------------------------
__global__ __launch_bounds__(256) void norm_gate(const float* __restrict__ nw) {
    int blk = blockIdx.x;
    int hq  = blk & 3;
    int bt  = blk >> 2;
    int tid = threadIdx.x;
    int hh  = tid >> 6;
    int c   = tid & 63;
    int ch  = hq * 256 + tid;
    size_t idx = (size_t)bt * DD + ch;

    float o  = g_o[idx];
    float ss = o * o;
#pragma unroll
    for (int m = 16; m; m >>= 1) ss += __shfl_xor_sync(0xffffffffu, ss, m);
    __shared__ float red[8];
    if ((tid & 31) == 0) red[tid >> 5] = ss;
    __syncthreads();
    float tot = red[hh * 2] + red[hh * 2 + 1];
    float inv = rsqrtf(tot * (1.f / 64.f) + 1e-5f);
    o *= inv * nw[c];
    float gt = g_gpre[idx];
    o *= gt / (1.f + expf(-gt));

    __nv_bfloat16 hi = __float2bfloat16(o);
    __nv_bfloat16 lo = __float2bfloat16(o - __bfloat162float(hi));
    size_t b = (size_t)bt * KBIG + ch;
    g_Ao[b]          = hi;
    g_Ao[b + DD]     = lo;
    g_Ao[b + 2 * DD] = hi;
}

// ---------------------------------------------------------------------------
// Launch: x Wq Wk Wv Wo Wg Wb cq_w cq_b ck_w ck_b cv_w cv_b nw
// ---------------------------------------------------------------------------
extern "C" void kernel_launch(void* const* d_in, const int* in_sizes, int n_in,
                              void* d_out, int out_size) {
    const float* x    = (const float*)d_in[0];
    const float* Wq   = (const float*)d_in[1];
    const float* Wk   = (const float*)d_in[2];
    const float* Wv   = (const float*)d_in[3];
    const float* Wo   = (const float*)d_in[4];
    const float* Wg   = (const float*)d_in[5];
    const float* Wb   = (const float*)d_in[6];
    const float* cq_w = (const float*)d_in[7];
    const float* cq_b = (const float*)d_in[8];
    const float* ck_w = (const float*)d_in[9];
    const float* ck_b = (const float*)d_in[10];
    const float* cv_w = (const float*)d_in[11];
    const float* cv_b = (const float*)d_in[12];
    const float* nw   = (const float*)d_in[13];
    float* out = (float*)d_out;

    cudaFuncSetAttribute(proj_mma, cudaFuncAttributeMaxDynamicSharedMemorySize, DSM_BYTES);
    cudaFuncSetAttribute(out_mma,  cudaFuncAttributeMaxDynamicSharedMemorySize, DSM_BYTES);

    split_x<<<BT, 256>>>(x);
    split_w<<<dim3(32, 32, 5), dim3(32, 32)>>>(Wq, Wk, Wv, Wg, Wo);
    split_wb<<<128, 256>>>(Wb);

    // z 0..3: projections; z 4: beta slice (only x-tile 0 active)
    proj_mma<<<dim3(DD / GBN, BT / GBM, 5), 256, DSM_BYTES>>>();
    beta_sig<<<BT * HH / 256, 256>>>();

    conv_norm<<<dim3(BT * 4, 1, 3), 256>>>(cq_w, cq_b, ck_w, ck_b, cv_w, cv_b);
    scan_kernel<<<512, 32>>>();
    norm_gate<<<BT * 4, 256>>>(nw);

    out_mma<<<dim3(DD / GBN, BT / GBM), 256, DSM_BYTES>>>(out);
}

// round 17
// speedup vs baseline: 1.2564x; 1.2564x over previous
#include <cuda_runtime.h>
#include <cuda_bf16.h>
#include <cstdint>

// Problem constants
#define BB    2
#define TT    2048
#define DD    1024
#define HH    16
#define DH    64
#define BT    (BB*TT)          // 4096
#define KBIG  3072             // 3 * DD (split-in-K bf16 GEMM)
#define NELE  ((size_t)BT*DD)  // 4,194,304

// ---------------------------------------------------------------------------
// Scratch (no cudaMalloc allowed -> __device__ globals)
// ---------------------------------------------------------------------------
__device__ float g_qpre[NELE];
__device__ float g_kpre[NELE];
__device__ float g_vpre[NELE];
__device__ float g_gpre[NELE];
__device__ float g_qn[NELE];
__device__ float g_kn[NELE];
__device__ float g_vn[NELE];
__device__ float g_o[NELE];
__device__ float g_bpre[(size_t)BT*128];   // beta pre-activation (cols 0..15 used)

// bf16 split operands for tensor-core GEMMs
__device__ __align__(16) __nv_bfloat16 g_Ax[(size_t)BT*KBIG];      // [Ah|Al|Ah] of x
__device__ __align__(16) __nv_bfloat16 g_Ao[(size_t)BT*KBIG];      // [Ah|Al|Ah] of o*gate
__device__ __align__(16) __nv_bfloat16 g_Bw[5][(size_t)DD*KBIG];   // W^T splits: [Bh|Bh|Bl]
__device__ __align__(16) __nv_bfloat16 g_Bwb[(size_t)128*KBIG];    // Wb^T split (16 rows + zeros)

// ---------------------------------------------------------------------------
// Small helpers
// ---------------------------------------------------------------------------
__device__ __forceinline__ uint32_t smem_u32(const void* p) {
    uint32_t a;
    asm("{ .reg .u64 t; cvta.to.shared.u64 t, %1; cvt.u32.u64 %0, t; }"
        : "=r"(a) : "l"(p));
    return a;
}
__device__ __forceinline__ unsigned sw128(unsigned o) { return o ^ ((o >> 3) & 0x70); }
__device__ __forceinline__ void cpa16(unsigned dst, const void* src) {
    asm volatile("cp.async.cg.shared.global [%0], [%1], 16;\n" ::"r"(dst), "l"(src));
}
__device__ __forceinline__ void ldsm4(uint32_t* r, uint32_t addr) {
    asm volatile("ldmatrix.sync.aligned.m8n8.x4.shared.b16 {%0,%1,%2,%3}, [%4];"
                 : "=r"(r[0]), "=r"(r[1]), "=r"(r[2]), "=r"(r[3]) : "r"(addr));
}
__device__ __forceinline__ void mma_bf16(float* d, const uint32_t* a, const uint32_t* b) {
    asm volatile(
        "mma.sync.aligned.m16n8k16.row.col.f32.bf16.bf16.f32 "
        "{%0,%1,%2,%3}, {%4,%5,%6,%7}, {%8,%9}, {%0,%1,%2,%3};"
        : "+f"(d[0]), "+f"(d[1]), "+f"(d[2]), "+f"(d[3])
        : "r"(a[0]), "r"(a[1]), "r"(a[2]), "r"(a[3]), "r"(b[0]), "r"(b[1]));
}

// ---------------------------------------------------------------------------
// Split kernels: x -> g_Ax ([hi|lo|hi]),  W -> W^T splits ([hi|hi|lo])
// ---------------------------------------------------------------------------
__global__ __launch_bounds__(256) void split_x(const float* __restrict__ x) {
    int row = blockIdx.x;
    int c0  = threadIdx.x * 4;
    float4 v = *(const float4*)(x + (size_t)row * DD + c0);
    float vv[4] = {v.x, v.y, v.z, v.w};
    size_t b = (size_t)row * KBIG + c0;
#pragma unroll
    for (int j = 0; j < 4; j++) {
        __nv_bfloat16 hi = __float2bfloat16(vv[j]);
        __nv_bfloat16 lo = __float2bfloat16(vv[j] - __bfloat162float(hi));
        g_Ax[b + j]          = hi;
        g_Ax[b + DD + j]     = lo;
        g_Ax[b + 2 * DD + j] = hi;
    }
}

__global__ __launch_bounds__(1024) void split_w(const float* __restrict__ Wq,
                                                const float* __restrict__ Wk,
                                                const float* __restrict__ Wv,
                                                const float* __restrict__ Wg,
                                                const float* __restrict__ Wo) {
    const float* W;
    switch (blockIdx.z) {
        case 0: W = Wq; break;
        case 1: W = Wk; break;
        case 2: W = Wv; break;
        case 3: W = Wg; break;
        default: W = Wo; break;
    }
    __nv_bfloat16* Bt = g_Bw[blockIdx.z];
    __shared__ float tile[32][33];
    int tx = threadIdx.x, ty = threadIdx.y;
    int k = blockIdx.y * 32 + ty, n = blockIdx.x * 32 + tx;
    tile[ty][tx] = W[(size_t)k * DD + n];
    __syncthreads();
    int nn = blockIdx.x * 32 + ty, kk = blockIdx.y * 32 + tx;
    float v = tile[tx][ty];  // = W[kk][nn]
    __nv_bfloat16 hi = __float2bfloat16(v);
    __nv_bfloat16 lo = __float2bfloat16(v - __bfloat162float(hi));
    size_t b = (size_t)nn * KBIG + kk;
    Bt[b]          = hi;
    Bt[b + DD]     = hi;
    Bt[b + 2 * DD] = lo;
}

// Wb (1024,16) -> g_Bwb rows 0..15 = [hi|hi|lo] of Wb columns; rows 16..127 zero.
__global__ __launch_bounds__(256) void split_wb(const float* __restrict__ Wb) {
    int n = blockIdx.x;  // 0..127
    __nv_bfloat16* row = g_Bwb + (size_t)n * KBIG;
    if (n < 16) {
        for (int k = threadIdx.x; k < DD; k += 256) {
            float v = Wb[(size_t)k * HH + n];
            __nv_bfloat16 hi = __float2bfloat16(v);
            __nv_bfloat16 lo = __float2bfloat16(v - __bfloat162float(hi));
            row[k]          = hi;
            row[k + DD]     = hi;
            row[k + 2 * DD] = lo;
        }
    } else {
        for (int k = threadIdx.x; k < KBIG; k += 256)
            row[k] = __float2bfloat16(0.f);
    }
}

// ---------------------------------------------------------------------------
// bf16 tensor-core GEMM via mma.sync (portable HMMA; tcgen05 PTX rejected by
// this harness's .target sm_103).
// C[M,N] = A[M,KBIG] * Bt[N,KBIG]^T, fp32 out, row stride ldc.
// CTA tile 128x128, BK=64, SW128 smem, 3-stage cp.async ring, one bar/stage.
// __launch_bounds__(256,2): 2 CTAs/SM.
// ---------------------------------------------------------------------------
#define GBM   128
#define GBN   128
#define GBK   64
#define NSTG  3
#define NS    (KBIG/GBK)            // 48
#define STG_A (GBM*128)             // 16384 B
#define STG_B (GBN*128)             // 16384 B
#define STG_BYTES (STG_A + STG_B)   // 32768 B
#define DSM_BYTES (NSTG*STG_BYTES + 1024)

__device__ __forceinline__ void gemm_mma_body(const __nv_bfloat16* __restrict__ A,
                                              const __nv_bfloat16* __restrict__ Bt,
                                              float* __restrict__ C, int ldc) {
    extern __shared__ char dynsm[];
    const uint32_t smb = (smem_u32(dynsm) + 1023u) & ~1023u;
    const int tid = threadIdx.x;
    const int wid = tid >> 5, lid = tid & 31;
    const int bm = blockIdx.y * GBM;
    const int bn = blockIdx.x * GBN;
    const int wm = (wid & 3) * 32;
    const int wn = (wid >> 2) * 64;

    float acc[2][8][4];
#pragma unroll
    for (int i = 0; i < 2; i++)
#pragma unroll
        for (int j = 0; j < 8; j++)
#pragma unroll
            for (int q = 0; q < 4; q++) acc[i][j][q] = 0.f;

    auto load_stage = [&](int st, int slot) {
        unsigned baseA = smb + slot * STG_BYTES;
        unsigned baseB = baseA + STG_A;
        const __nv_bfloat16* Ab = A + (size_t)bm * KBIG + st * GBK;
        const __nv_bfloat16* Bb = Bt + (size_t)bn * KBIG + st * GBK;
#pragma unroll
        for (int c = tid; c < 1024; c += 256) {
            int r = c >> 3, ci = c & 7;
            cpa16(baseA + sw128(r * 128 + ci * 16), Ab + (size_t)r * KBIG + ci * 8);
        }
#pragma unroll
        for (int c = tid; c < 1024; c += 256) {
            int r = c >> 3, ci = c & 7;
            cpa16(baseB + sw128(r * 128 + ci * 16), Bb + (size_t)r * KBIG + ci * 8);
        }
    };

    const int a_row = (lid & 15);
    const int a_kb  = (lid >> 4) * 16;
    const int b_row = (lid & 7) + (lid >> 4) * 8;
    const int b_kb  = ((lid >> 3) & 1) * 16;

    load_stage(0, 0);
    asm volatile("cp.async.commit_group;\n" ::: "memory");
    load_stage(1, 1);
    asm volatile("cp.async.commit_group;\n" ::: "memory");

    for (int i = 0; i < NS; i++) {
        const int slot = i % NSTG;
        asm volatile("cp.async.wait_group 1;\n" ::: "memory");
        __syncthreads();

        if (i + 2 < NS) load_stage(i + 2, (i + 2) % NSTG);
        asm volatile("cp.async.commit_group;\n" ::: "memory");

        const unsigned baseA = smb + slot * STG_BYTES;
        const unsigned baseB = baseA + STG_A;

#pragma unroll
        for (int ks = 0; ks < 4; ks++) {
            uint32_t af[2][4];
#pragma unroll
            for (int mt = 0; mt < 2; mt++)
                ldsm4(af[mt],
                      baseA + sw128((wm + mt * 16 + a_row) * 128 + ks * 32 + a_kb));
            uint32_t bfr[4][4];
#pragma unroll
            for (int nt = 0; nt < 4; nt++)
                ldsm4(bfr[nt],
                      baseB + sw128((wn + nt * 16 + b_row) * 128 + ks * 32 + b_kb));
#pragma unroll
            for (int mt = 0; mt < 2; mt++)
#pragma unroll
                for (int n8 = 0; n8 < 8; n8++)
                    mma_bf16(acc[mt][n8], af[mt], &bfr[n8 >> 1][(n8 & 1) * 2]);
        }
    }

    const int g   = lid >> 2;
    const int tig = lid & 3;
#pragma unroll
    for (int mt = 0; mt < 2; mt++) {
#pragma unroll
        for (int n8 = 0; n8 < 8; n8++) {
            int row = bm + wm + mt * 16 + g;
            int col = bn + wn + n8 * 8 + tig * 2;
            float2 lo = make_float2(acc[mt][n8][0], acc[mt][n8][1]);
            float2 hi = make_float2(acc[mt][n8][2], acc[mt][n8][3]);
            *(float2*)(C + (size_t)row * ldc + col)       = lo;
            *(float2*)(C + (size_t)(row + 8) * ldc + col) = hi;
        }
    }
}

// z = 0..3: q/k/v/g projections (N=1024). z = 4: beta slice (N=128, x-tile 0 only).
__global__ __launch_bounds__(256, 2) void proj_mma() {
    if (blockIdx.z == 4) {
        if (blockIdx.x != 0) return;
        gemm_mma_body(g_Ax, g_Bwb, g_bpre, 128);
        return;
    }
    float* C;
    switch (blockIdx.z) {
        case 0:  C = g_qpre; break;
        case 1:  C = g_kpre; break;
        case 2:  C = g_vpre; break;
        default: C = g_gpre; break;
    }
    gemm_mma_body(g_Ax, g_Bw[blockIdx.z], C, DD);
}

__global__ __launch_bounds__(256, 2) void out_mma(float* __restrict__ out) {
    gemm_mma_body(g_Ao, g_Bw[4], out, DD);
}

// ---------------------------------------------------------------------------
// Depthwise causal conv(k=4) + bias + silu, then (for q,k) per-head l2norm.
// Fused: blockIdx.z = mode (0=q, 1=k, 2=v).
// ---------------------------------------------------------------------------
__global__ __launch_bounds__(256) void conv_norm(const float* __restrict__ cq_w,
                                                 const float* __restrict__ cq_b,
                                                 const float* __restrict__ ck_w,
                                                 const float* __restrict__ ck_b,
                                                 const float* __restrict__ cv_w,
                                                 const float* __restrict__ cv_b) {
    int mode = blockIdx.z;
    const float* pre = (mode == 0) ? g_qpre : (mode == 1) ? g_kpre : g_vpre;
    float* out       = (mode == 0) ? g_qn   : (mode == 1) ? g_kn   : g_vn;
    const float* cw  = (mode == 0) ? cq_w   : (mode == 1) ? ck_w   : cv_w;
    const float* cb  = (mode == 0) ? cq_b   : (mode == 1) ? ck_b   : cv_b;

    int blk = blockIdx.x;
    int hq  = blk & 3;
    int bt  = blk >> 2;
    int t   = bt & (TT - 1);
    int b   = bt >> 11;
    int tid = threadIdx.x;
    int hh  = tid >> 6;
    int ch  = hq * 256 + tid;

    float acc = cb[ch];
#pragma unroll
    for (int j = 0; j < 4; j++) {
        int tt = t - 3 + j;
        if (tt >= 0)
            acc = fmaf(pre[(size_t)(b * TT + tt) * DD + ch], cw[ch * 4 + j], acc);
    }
    float y = acc / (1.f + expf(-acc));  // silu

    if (mode < 2) {
        float ss = y * y;
#pragma unroll
        for (int m = 16; m; m >>= 1) ss += __shfl_xor_sync(0xffffffffu, ss, m);
        __shared__ float red[8];
        if ((tid & 31) == 0) red[tid >> 5] = ss;
        __syncthreads();
        float tot = red[hh * 2] + red[hh * 2 + 1];
        float inv = rsqrtf(tot + 1e-6f);
        if (mode == 0) inv *= 0.125f;
        y *= inv;
    }
    out[(size_t)bt * DD + ch] = y;
}

// ---------------------------------------------------------------------------
// Sequential delta-rule scan — 2-STEP LOOKAHEAD.
// CTA = (b, h, 16-col v-slice); 256 threads = 16 rowgroups x 16 cols; thread
// holds rows [4g,4g+4) of state column v0+vl.
// Per iteration processes steps (2i, 2i+1). All 8 pair dot-products depend
// only on S_{2i-1}, so ONE batched 4-level butterfly covers both steps:
//   p1  = k1.S + (k1.k0) err0,  po1 = q1.S + (q1.k0) err0,
//   o1  = po1 + (q1.q1-dot k1) err1.
// Pair-granular triple buffering, one barrier per PAIR. Sigmoid(beta) inline.
// ---------------------------------------------------------------------------
__device__ __forceinline__ void cpa4(void* smem, const void* g) {
    unsigned sa = (unsigned)__cvta_generic_to_shared(smem);
    asm volatile("cp.async.ca.shared.global [%0], [%1], 4;\n" ::"r"(sa), "l"(g));
}

__global__ __launch_bounds__(256) void scan_kernel() {
    int blk = blockIdx.x;
    int sv  = blk & 3;
    int bh  = blk >> 2;
    int b   = bh >> 4, h = bh & 15;
    int v0  = sv * 16;
    int tid = threadIdx.x;
    int g   = tid & 15;
    int vl  = tid >> 4;

    __shared__ __align__(16) float buf[3][2][160];

    const size_t base = (size_t)b * TT * DD + h * DH;
    const float* Kp = g_kn + base;
    const float* Qp = g_qn + base;
    const float* Vp = g_vn + base + v0;
    const float* Bp = g_bpre + (size_t)b * TT * 128 + h;
    float* Op = g_o + base + v0;

    auto issue = [&](int t, int pr, int sb) {
        float* dst = buf[pr][sb];
        if (tid < 64)        cpa4(&dst[tid], Kp + (size_t)t * DD + tid);
        else if (tid < 128)  cpa4(&dst[tid], Qp + (size_t)t * DD + (tid - 64));
        else if (tid < 144)  cpa4(&dst[tid], Vp + (size_t)t * DD + (tid - 128));
        else if (tid == 144) cpa4(&dst[144], Bp + (size_t)t * 128);
    };

    issue(0, 0, 0);
    issue(1, 0, 1);
    asm volatile("cp.async.commit_group;\n" ::: "memory");
    issue(2, 1, 0);
    issue(3, 1, 1);
    asm volatile("cp.async.commit_group;\n" ::: "memory");

    float s0 = 0.f, s1 = 0.f, s2 = 0.f, s3 = 0.f;

    for (int i = 0; i < TT / 2; i++) {
        const int pr = i % 3;
        asm volatile("cp.async.wait_group 1;\n" ::: "memory");
        __syncthreads();

        float4 k0 = *(const float4*)&buf[pr][0][g * 4];
        float4 q0 = *(const float4*)&buf[pr][0][64 + g * 4];
        float  vt0 = buf[pr][0][128 + vl];
        float  bb0 = buf[pr][0][144];
        float4 k1 = *(const float4*)&buf[pr][1][g * 4];
        float4 q1 = *(const float4*)&buf[pr][1][64 + g * 4];
        float  vt1 = buf[pr][1][128 + vl];
        float  bb1 = buf[pr][1][144];

        bb0 = 1.f / (1.f + expf(-bb0));
        bb1 = 1.f / (1.f + expf(-bb1));

        // 8 partial dots (all vs S_{t-1}); reduced together, one butterfly.
        float r[8];
        r[0] = fmaf(k0.x, s0, fmaf(k0.y, s1, fmaf(k0.z, s2, k0.w * s3)));  // k0.S
        r[1] = fmaf(q0.x, s0, fmaf(q0.y, s1, fmaf(q0.z, s2, q0.w * s3)));  // q0.S
        r[2] = fmaf(q0.x, k0.x, fmaf(q0.y, k0.y, fmaf(q0.z, k0.z, q0.w * k0.w)));  // q0.k0
        r[3] = fmaf(k1.x, s0, fmaf(k1.y, s1, fmaf(k1.z, s2, k1.w * s3)));  // k1.S
        r[4] = fmaf(q1.x, s0, fmaf(q1.y, s1, fmaf(q1.z, s2, q1.w * s3)));  // q1.S
        r[5] = fmaf(k1.x, k0.x, fmaf(k1.y, k0.y, fmaf(k1.z, k0.z, k1.w * k0.w)));  // k1.k0
        r[6] = fmaf(q1.x, k0.x, fmaf(q1.y, k0.y, fmaf(q1.z, k0.z, q1.w * k0.w)));  // q1.k0
        r[7] = fmaf(q1.x, k1.x, fmaf(q1.y, k1.y, fmaf(q1.z, k1.z, q1.w * k1.w)));  // q1.k1

#pragma unroll
        for (int m = 1; m <= 8; m <<= 1)
#pragma unroll
            for (int j = 0; j < 8; j++)
                r[j] += __shfl_xor_sync(0xffffffffu, r[j], m);

        float err0 = (vt0 - r[0]) * bb0;
        float o0   = fmaf(r[2], err0, r[1]);
        float p1   = fmaf(r[5], err0, r[3]);
        float err1 = (vt1 - p1) * bb1;
        float po1  = fmaf(r[6], err0, r[4]);
        float o1   = fmaf(r[7], err1, po1);

        if (g == 0) {
            Op[(size_t)(2 * i) * DD + vl]     = o0;
            Op[(size_t)(2 * i + 1) * DD + vl] = o1;
        }

        s0 = fmaf(k1.x, err1, fmaf(k0.x, err0, s0));
        s1 = fmaf(k1.y, err1, fmaf(k0.y, err0, s1));
        s2 = fmaf(k1.z, err1, fmaf(k0.z, err0, s2));
        s3 = fmaf(k1.w, err1, fmaf(k0.w, err0, s3));

        // prefetch pair i+2 into slot (i+2)%3 == slot read at i-1 (readers
        // passed this iteration's barrier) -> safe with one barrier per pair.
        if (2 * i + 4 < TT) {
            int np = (i + 2) % 3;
            issue(2 * i + 4, np, 0);
            issue(2 * i + 5, np, 1);
        }
        asm volatile("cp.async.commit_group;\n" ::: "memory");
    }
}

// ---------------------------------------------------------------------------
// RMSNorm over head_dim + silu gate -> bf16 split rows of g_Ao
// ---------------------------------------------------------------------------
__global__ __launch_bounds__(256) void norm_gate(const float* __restrict__ nw) {
    int blk = blockIdx.x;
    int hq  = blk & 3;
    int bt  = blk >> 2;
    int tid = threadIdx.x;
    int hh  = tid >> 6;
    int c   = tid & 63;
    int ch  = hq * 256 + tid;
    size_t idx = (size_t)bt * DD + ch;

    float o  = g_o[idx];
    float ss = o * o;
#pragma unroll
    for (int m = 16; m; m >>= 1) ss += __shfl_xor_sync(0xffffffffu, ss, m);
    __shared__ float red[8];
    if ((tid & 31) == 0) red[tid >> 5] = ss;
    __syncthreads();
    float tot = red[hh * 2] + red[hh * 2 + 1];
    float inv = rsqrtf(tot * (1.f / 64.f) + 1e-5f);
    o *= inv * nw[c];
    float gt = g_gpre[idx];
    o *= gt / (1.f + expf(-gt));

    __nv_bfloat16 hi = __float2bfloat16(o);
    __nv_bfloat16 lo = __float2bfloat16(o - __bfloat162float(hi));
    size_t b = (size_t)bt * KBIG + ch;
    g_Ao[b]          = hi;
    g_Ao[b + DD]     = lo;
    g_Ao[b + 2 * DD] = hi;
}

// ---------------------------------------------------------------------------
// Launch: x Wq Wk Wv Wo Wg Wb cq_w cq_b ck_w ck_b cv_w cv_b nw
// ---------------------------------------------------------------------------
extern "C" void kernel_launch(void* const* d_in, const int* in_sizes, int n_in,
                              void* d_out, int out_size) {
    const float* x    = (const float*)d_in[0];
    const float* Wq   = (const float*)d_in[1];
    const float* Wk   = (const float*)d_in[2];
    const float* Wv   = (const float*)d_in[3];
    const float* Wo   = (const float*)d_in[4];
    const float* Wg   = (const float*)d_in[5];
    const float* Wb   = (const float*)d_in[6];
    const float* cq_w = (const float*)d_in[7];
    const float* cq_b = (const float*)d_in[8];
    const float* ck_w = (const float*)d_in[9];
    const float* ck_b = (const float*)d_in[10];
    const float* cv_w = (const float*)d_in[11];
    const float* cv_b = (const float*)d_in[12];
    const float* nw   = (const float*)d_in[13];
    float* out = (float*)d_out;

    cudaFuncSetAttribute(proj_mma, cudaFuncAttributeMaxDynamicSharedMemorySize, DSM_BYTES);
    cudaFuncSetAttribute(out_mma,  cudaFuncAttributeMaxDynamicSharedMemorySize, DSM_BYTES);

    split_x<<<BT, 256>>>(x);
    split_w<<<dim3(32, 32, 5), dim3(32, 32)>>>(Wq, Wk, Wv, Wg, Wo);
    split_wb<<<128, 256>>>(Wb);

    // z 0..3: projections; z 4: beta slice (only x-tile 0 active)
    proj_mma<<<dim3(DD / GBN, BT / GBM, 5), 256, DSM_BYTES>>>();

    conv_norm<<<dim3(BT * 4, 1, 3), 256>>>(cq_w, cq_b, ck_w, ck_b, cv_w, cv_b);
    scan_kernel<<<BB * HH * 4, 256>>>();
    norm_gate<<<BT * 4, 256>>>(nw);

    out_mma<<<dim3(DD / GBN, BT / GBM), 256, DSM_BYTES>>>(out);
}